// round 2
// baseline (speedup 1.0000x reference)
#include <cuda_runtime.h>
#include <math.h>

#define BATCH    4
#define N_TOK    16384
#define D        192
#define DFF      768
#define HEADS    6
#define DH       32
#define M_CL     64
#define KC       (N_TOK / M_CL)      // 256
#define BN_ROWS  (BATCH * N_TOK)     // 65536
#define GRID_W   128

// ---------------- scratch (static device globals; no allocations) ----------
__device__ float g_xn [BN_ROWS * D];        // LN output          (50 MB)
__device__ float g_qkv[BN_ROWS * 3 * D];    // curve-ordered qkv  (151 MB)
__device__ float g_o  [BN_ROWS * D];        // attn out, token order (50 MB)
__device__ float g_h  [BN_ROWS * DFF];      // MLP hidden         (201 MB)
__device__ int   g_ord[BN_ROWS];            // rank  -> token row
__device__ int   g_inv[BN_ROWS];            // token -> rank row

// ---------------- order: keys are a permutation of 0..n-1, no sort ---------
__global__ void order_kernel(const float* __restrict__ pos) {
    int i = blockIdx.x * blockDim.x + threadIdx.x;
    if (i >= BN_ROWS) return;
    int b = i / N_TOK;
    float px = pos[(size_t)i * 2 + 0];
    float py = pos[(size_t)i * 2 + 1];
    int ix = (int)floorf(px);
    int iy = (int)floorf(py);
    int key = iy * GRID_W + ((iy & 1) ? (GRID_W - 1 - ix) : ix);
    int rank = b * N_TOK + key;
    g_inv[i]    = rank;   // token row -> ordered row
    g_ord[rank] = i;      // ordered row -> token row
}

// ---------------- layernorm: one warp per token ----------------------------
__global__ void ln_kernel(const float* __restrict__ x,
                          const float* __restrict__ gamma,
                          const float* __restrict__ beta,
                          float* __restrict__ out) {
    int warp = (blockIdx.x * blockDim.x + threadIdx.x) >> 5;
    int lane = threadIdx.x & 31;
    if (warp >= BN_ROWS) return;
    const float* xr = x + (size_t)warp * D;
    float v[6];
    float s = 0.f, s2 = 0.f;
#pragma unroll
    for (int j = 0; j < 6; j++) {
        v[j] = xr[lane + 32 * j];
        s += v[j];
        s2 += v[j] * v[j];
    }
#pragma unroll
    for (int o = 16; o; o >>= 1) {
        s  += __shfl_xor_sync(0xffffffffu, s,  o);
        s2 += __shfl_xor_sync(0xffffffffu, s2, o);
    }
    float mean = s * (1.f / D);
    float var  = s2 * (1.f / D) - mean * mean;
    float rstd = rsqrtf(var + 1e-5f);
    float* orow = out + (size_t)warp * D;
#pragma unroll
    for (int j = 0; j < 6; j++) {
        int c = lane + 32 * j;
        orow[c] = (v[j] - mean) * rstd * gamma[c] + beta[c];
    }
}

// ---------------- generic tiled sgemm: C = act(A@W + bias) [+res], scatter --
__device__ __forceinline__ float gelu_tanh(float v) {
    float c = v + 0.044715f * v * v * v;
    return 0.5f * v * (1.f + tanhf(0.7978845608028654f * c));
}

// 64x64 block tile, BK=16, 256 threads, 4x4 per thread.
// ACT: 0 none, 1 gelu. SCATTER: write row omap[row]. RES: add res at output row.
template <int ACT, bool SCATTER, bool RES>
__global__ void gemm_kernel(const float* __restrict__ A,
                            const float* __restrict__ W,
                            const float* __restrict__ bias,
                            const float* __restrict__ res,
                            const int*   __restrict__ omap,
                            float* __restrict__ C,
                            int K, int N) {
    __shared__ float As[16][64];   // transposed A tile
    __shared__ float Bs[16][64];

    int tid    = threadIdx.x;
    int row_t  = (tid >> 4) << 2;   // 0..60
    int col_t  = (tid & 15) << 2;   // 0..60
    int mbase  = blockIdx.y * 64;
    int nbase  = blockIdx.x * 64;

    float acc[4][4];
#pragma unroll
    for (int i = 0; i < 4; i++)
#pragma unroll
        for (int j = 0; j < 4; j++) acc[i][j] = 0.f;

    int ar = tid >> 2;            // 0..63 (A tile row)
    int ak = (tid & 3) << 2;      // 0,4,8,12 (A tile col base)
    int wr = tid >> 4;            // 0..15 (W tile row)
    int wc = (tid & 15) << 2;     // 0..60 (W tile col base)

    for (int k0 = 0; k0 < K; k0 += 16) {
        float4 a = *(const float4*)&A[(size_t)(mbase + ar) * K + k0 + ak];
        As[ak + 0][ar] = a.x;
        As[ak + 1][ar] = a.y;
        As[ak + 2][ar] = a.z;
        As[ak + 3][ar] = a.w;
        *(float4*)&Bs[wr][wc] = *(const float4*)&W[(size_t)(k0 + wr) * N + nbase + wc];
        __syncthreads();
#pragma unroll
        for (int kk = 0; kk < 16; kk++) {
            float4 av = *(const float4*)&As[kk][row_t];
            float4 bv = *(const float4*)&Bs[kk][col_t];
            float a4[4] = {av.x, av.y, av.z, av.w};
            float b4[4] = {bv.x, bv.y, bv.z, bv.w};
#pragma unroll
            for (int i = 0; i < 4; i++)
#pragma unroll
                for (int j = 0; j < 4; j++)
                    acc[i][j] += a4[i] * b4[j];
        }
        __syncthreads();
    }

#pragma unroll
    for (int i = 0; i < 4; i++) {
        int row  = mbase + row_t + i;
        int orow = SCATTER ? omap[row] : row;
#pragma unroll
        for (int j = 0; j < 4; j++) {
            int col = nbase + col_t + j;
            float v = acc[i][j] + bias[col];
            if (ACT == 1) v = gelu_tanh(v);
            if (RES) v += res[(size_t)orow * N + col];
            C[(size_t)orow * N + col] = v;
        }
    }
}

// ---------------- cluster attention: one block per (b, cluster, head) ------
__global__ void attn_kernel(const float* __restrict__ qkv, float* __restrict__ o) {
    int hidx = blockIdx.x % HEADS;
    int c    = (blockIdx.x / HEADS) % KC;
    int b    = blockIdx.x / (HEADS * KC);
    int i    = threadIdx.x;               // query row 0..63

    __shared__ float Ks[M_CL][DH];
    __shared__ float Vs[M_CL][DH];
    __shared__ float Ss[M_CL][M_CL + 1];

    size_t base = (size_t)(b * N_TOK + c * M_CL) * (3 * D);
    const float* kr = qkv + base + (size_t)i * (3 * D) + D     + hidx * DH;
    const float* vr = qkv + base + (size_t)i * (3 * D) + 2 * D + hidx * DH;
#pragma unroll
    for (int d4 = 0; d4 < DH; d4 += 4) {
        *(float4*)&Ks[i][d4] = *(const float4*)&kr[d4];
        *(float4*)&Vs[i][d4] = *(const float4*)&vr[d4];
    }
    float q[DH];
    const float* qr = qkv + base + (size_t)i * (3 * D) + hidx * DH;
#pragma unroll
    for (int d = 0; d < DH; d++) q[d] = qr[d];
    __syncthreads();

    const float scale = 0.17677669529663687f;   // 1/sqrt(32)
    float mx = -1e30f;
#pragma unroll 4
    for (int j = 0; j < M_CL; j++) {
        float s = 0.f;
#pragma unroll
        for (int d = 0; d < DH; d++) s += q[d] * Ks[j][d];
        s *= scale;
        Ss[i][j] = s;
        mx = fmaxf(mx, s);
    }
    float sum = 0.f;
#pragma unroll 4
    for (int j = 0; j < M_CL; j++) {
        float p = expf(Ss[i][j] - mx);
        Ss[i][j] = p;
        sum += p;
    }
    float inv = 1.f / sum;
    float accd[DH];
#pragma unroll
    for (int d = 0; d < DH; d++) accd[d] = 0.f;
#pragma unroll 4
    for (int j = 0; j < M_CL; j++) {
        float p = Ss[i][j];
#pragma unroll
        for (int d = 0; d < DH; d++) accd[d] += p * Vs[j][d];
    }

    int rank = b * N_TOK + c * M_CL + i;
    int tok  = g_ord[rank];
    float* orow = o + (size_t)tok * D + hidx * DH;
#pragma unroll
    for (int d = 0; d < DH; d++) orow[d] = accd[d] * inv;
}

// ---------------- launch ----------------------------------------------------
extern "C" void kernel_launch(void* const* d_in, const int* in_sizes, int n_in,
                              void* d_out, int out_size) {
    const float* x      = (const float*)d_in[0];
    const float* pos    = (const float*)d_in[1];
    const float* ln1_g  = (const float*)d_in[2];
    const float* ln1_b  = (const float*)d_in[3];
    const float* w_qkv  = (const float*)d_in[4];
    const float* b_qkv  = (const float*)d_in[5];
    const float* w_proj = (const float*)d_in[6];
    const float* b_proj = (const float*)d_in[7];
    const float* ln2_g  = (const float*)d_in[8];
    const float* ln2_b  = (const float*)d_in[9];
    const float* w_fc1  = (const float*)d_in[10];
    const float* b_fc1  = (const float*)d_in[11];
    const float* w_fc2  = (const float*)d_in[12];
    const float* b_fc2  = (const float*)d_in[13];
    float* out = (float*)d_out;

    float *xn, *qkv, *o, *hbuf;
    int *inv;
    cudaGetSymbolAddress((void**)&xn,   g_xn);
    cudaGetSymbolAddress((void**)&qkv,  g_qkv);
    cudaGetSymbolAddress((void**)&o,    g_o);
    cudaGetSymbolAddress((void**)&hbuf, g_h);
    cudaGetSymbolAddress((void**)&inv,  g_inv);

    // running x lives in d_out
    cudaMemcpyAsync(out, x, sizeof(float) * (size_t)BN_ROWS * D,
                    cudaMemcpyDeviceToDevice, 0);

    order_kernel<<<BN_ROWS / 256, 256>>>(pos);

    dim3 gQKV(3 * D / 64, BN_ROWS / 64);   // (9, 1024)
    dim3 gPRJ(D / 64,     BN_ROWS / 64);   // (3, 1024)
    dim3 gFC1(DFF / 64,   BN_ROWS / 64);   // (12, 1024)
    dim3 gFC2(D / 64,     BN_ROWS / 64);   // (3, 1024)
    int lnBlocks = BN_ROWS / 8;            // 256 thr = 8 warps = 8 tokens/block

    for (int i = 0; i < 2; i++) {
        // attention branch
        ln_kernel<<<lnBlocks, 256>>>(out, ln1_g + i * D, ln1_b + i * D, xn);
        gemm_kernel<0, true, false><<<gQKV, 256>>>(
            xn, w_qkv + (size_t)i * D * 3 * D, b_qkv + i * 3 * D,
            nullptr, inv, qkv, D, 3 * D);
        attn_kernel<<<BATCH * KC * HEADS, M_CL>>>(qkv, o);
        gemm_kernel<0, false, true><<<gPRJ, 256>>>(
            o, w_proj + (size_t)i * D * D, b_proj + i * D,
            out, nullptr, out, D, D);
        // MLP branch
        ln_kernel<<<lnBlocks, 256>>>(out, ln2_g + i * D, ln2_b + i * D, xn);
        gemm_kernel<1, false, false><<<gFC1, 256>>>(
            xn, w_fc1 + (size_t)i * D * DFF, b_fc1 + i * DFF,
            nullptr, nullptr, hbuf, D, DFF);
        gemm_kernel<0, false, true><<<gFC2, 256>>>(
            hbuf, w_fc2 + (size_t)i * DFF * D, b_fc2 + i * D,
            out, nullptr, out, DFF, D);
    }
}

// round 3
// speedup vs baseline: 1.5146x; 1.5146x over previous
#include <cuda_runtime.h>
#include <mma.h>
#include <math.h>

using namespace nvcuda;

#define BATCH    4
#define N_TOK    16384
#define D        192
#define DFF      768
#define HEADS    6
#define DH       32
#define M_CL     64
#define KC       (N_TOK / M_CL)      // 256
#define BN_ROWS  (BATCH * N_TOK)     // 65536
#define GRID_W   128

// ---------------- scratch (static device globals; no allocations) ----------
__device__ float g_xn [BN_ROWS * D];
__device__ float g_qkv[BN_ROWS * 3 * D];
__device__ float g_o  [BN_ROWS * D];
__device__ float g_h  [BN_ROWS * DFF];
__device__ int   g_ord[BN_ROWS];            // rank  -> token row
__device__ int   g_inv[BN_ROWS];            // token -> rank row

// ---------------- order: keys are a permutation of 0..n-1, no sort ---------
__global__ void order_kernel(const float* __restrict__ pos) {
    int i = blockIdx.x * blockDim.x + threadIdx.x;
    if (i >= BN_ROWS) return;
    int b = i / N_TOK;
    int ix = (int)floorf(pos[(size_t)i * 2 + 0]);
    int iy = (int)floorf(pos[(size_t)i * 2 + 1]);
    int key = iy * GRID_W + ((iy & 1) ? (GRID_W - 1 - ix) : ix);
    int rank = b * N_TOK + key;
    g_inv[i]    = rank;
    g_ord[rank] = i;
}

// ---------------- layernorm: one warp per token ----------------------------
__global__ void ln_kernel(const float* __restrict__ x,
                          const float* __restrict__ gamma,
                          const float* __restrict__ beta,
                          float* __restrict__ out) {
    int warp = (blockIdx.x * blockDim.x + threadIdx.x) >> 5;
    int lane = threadIdx.x & 31;
    if (warp >= BN_ROWS) return;
    const float* xr = x + (size_t)warp * D;
    float v[6];
    float s = 0.f, s2 = 0.f;
#pragma unroll
    for (int j = 0; j < 6; j++) {
        v[j] = xr[lane + 32 * j];
        s += v[j];
        s2 += v[j] * v[j];
    }
#pragma unroll
    for (int o = 16; o; o >>= 1) {
        s  += __shfl_xor_sync(0xffffffffu, s,  o);
        s2 += __shfl_xor_sync(0xffffffffu, s2, o);
    }
    float mean = s * (1.f / D);
    float var  = s2 * (1.f / D) - mean * mean;
    float rstd = rsqrtf(var + 1e-5f);
    float* orow = out + (size_t)warp * D;
#pragma unroll
    for (int j = 0; j < 6; j++) {
        int c = lane + 32 * j;
        orow[c] = (v[j] - mean) * rstd * gamma[c] + beta[c];
    }
}

__device__ __forceinline__ float gelu_tanh(float v) {
    float c = v + 0.044715f * v * v * v;
    return 0.5f * v * (1.f + tanhf(0.7978845608028654f * c));
}

// ---------------- tf32 tensor-core GEMM: C = act(A@W + bias) [+res] --------
// Block tile 128x64, BK=32, 256 threads = 8 warps (4x2), warp tile 32x32
// (2x2 wmma m16n16k8 fragments).
#define BM 128
#define BN 64
#define BK 32
#define PAD_A 36
#define PAD_B 68

template <int ACT, bool SCATTER, bool RES>
__global__ __launch_bounds__(256) void gemm_tc(
        const float* __restrict__ A,
        const float* __restrict__ W,
        const float* __restrict__ bias,
        const float* __restrict__ res,
        const int*   __restrict__ omap,
        float* __restrict__ C,
        int K, int N) {
    __shared__ float smem[BM * PAD_B];            // 8704 floats, aliased
    float* As = smem;                              // [BM][PAD_A] = 4608
    float* Bs = smem + BM * PAD_A;                 // [BK][PAD_B] = 2176
    float* Cs = smem;                              // [BM][PAD_B] epilogue

    int tid  = threadIdx.x;
    int warp = tid >> 5;
    int mw   = warp >> 1;          // 0..3 -> M offset 32*mw
    int nw   = warp & 1;           // 0..1 -> N offset 32*nw
    int mbase = blockIdx.y * BM;
    int nbase = blockIdx.x * BN;

    wmma::fragment<wmma::accumulator, 16, 16, 8, float> acc[2][2];
#pragma unroll
    for (int i = 0; i < 2; i++)
#pragma unroll
        for (int j = 0; j < 2; j++) wmma::fill_fragment(acc[i][j], 0.f);

    for (int k0 = 0; k0 < K; k0 += BK) {
#pragma unroll
        for (int p = 0; p < 4; p++) {
            int row = (tid >> 3) + p * 32;
            int col = (tid & 7) * 4;
            float4 v = *(const float4*)&A[(size_t)(mbase + row) * K + k0 + col];
            *(float4*)&As[row * PAD_A + col] = v;
        }
#pragma unroll
        for (int p = 0; p < 2; p++) {
            int row = (tid >> 4) + p * 16;
            int col = (tid & 15) * 4;
            float4 v = *(const float4*)&W[(size_t)(k0 + row) * N + nbase + col];
            *(float4*)&Bs[row * PAD_B + col] = v;
        }
        __syncthreads();
#pragma unroll
        for (int kk = 0; kk < BK; kk += 8) {
            wmma::fragment<wmma::matrix_a, 16, 16, 8, wmma::precision::tf32,
                           wmma::row_major> af[2];
            wmma::fragment<wmma::matrix_b, 16, 16, 8, wmma::precision::tf32,
                           wmma::row_major> bf[2];
#pragma unroll
            for (int i = 0; i < 2; i++) {
                wmma::load_matrix_sync(af[i],
                    &As[(mw * 32 + 16 * i) * PAD_A + kk], PAD_A);
#pragma unroll
                for (int t = 0; t < af[i].num_elements; t++)
                    af[i].x[t] = wmma::__float_to_tf32(af[i].x[t]);
            }
#pragma unroll
            for (int j = 0; j < 2; j++) {
                wmma::load_matrix_sync(bf[j],
                    &Bs[kk * PAD_B + nw * 32 + 16 * j], PAD_B);
#pragma unroll
                for (int t = 0; t < bf[j].num_elements; t++)
                    bf[j].x[t] = wmma::__float_to_tf32(bf[j].x[t]);
            }
#pragma unroll
            for (int i = 0; i < 2; i++)
#pragma unroll
                for (int j = 0; j < 2; j++)
                    wmma::mma_sync(acc[i][j], af[i], bf[j], acc[i][j]);
        }
        __syncthreads();
    }

    // epilogue: stage to smem, then fused bias/act/res/scatter store
#pragma unroll
    for (int i = 0; i < 2; i++)
#pragma unroll
        for (int j = 0; j < 2; j++)
            wmma::store_matrix_sync(
                &Cs[(mw * 32 + 16 * i) * PAD_B + nw * 32 + 16 * j],
                acc[i][j], PAD_B, wmma::mem_row_major);
    __syncthreads();

    for (int idx = tid; idx < BM * BN; idx += 256) {
        int r  = idx >> 6;
        int cc = idx & 63;
        float v = Cs[r * PAD_B + cc] + bias[nbase + cc];
        if (ACT == 1) v = gelu_tanh(v);
        int orow = SCATTER ? omap[mbase + r] : (mbase + r);
        if (RES) v += res[(size_t)orow * N + nbase + cc];
        C[(size_t)orow * N + nbase + cc] = v;
    }
}

// ---------------- cluster attention: flash-style, no score buffer ----------
__global__ void attn_kernel(const float* __restrict__ qkv,
                            float* __restrict__ o) {
    int hidx = blockIdx.x % HEADS;
    int rem  = blockIdx.x / HEADS;
    int c    = rem % KC;
    int b    = rem / KC;
    int i    = threadIdx.x;               // query row 0..63

    __shared__ float4 Ks[M_CL][DH / 4];
    __shared__ float4 Vs[M_CL][DH / 4];

    size_t base = (size_t)(b * N_TOK + c * M_CL) * (3 * D);
    const float* row = qkv + base + (size_t)i * (3 * D) + hidx * DH;

    float4 q4[DH / 4];
#pragma unroll
    for (int d4 = 0; d4 < DH / 4; d4++) {
        q4[d4]    = ((const float4*)row)[d4];
        Ks[i][d4] = ((const float4*)(row + D))[d4];
        Vs[i][d4] = ((const float4*)(row + 2 * D))[d4];
    }
    __syncthreads();

    const float scale = 0.17677669529663687f;   // 1/sqrt(32)
    float acc[DH];
#pragma unroll
    for (int d = 0; d < DH; d++) acc[d] = 0.f;
    float sum = 0.f;

#pragma unroll 2
    for (int j = 0; j < M_CL; j++) {
        float s = 0.f;
#pragma unroll
        for (int d4 = 0; d4 < DH / 4; d4++) {
            float4 kv = Ks[j][d4];
            s += q4[d4].x * kv.x + q4[d4].y * kv.y
               + q4[d4].z * kv.z + q4[d4].w * kv.w;
        }
        float p = __expf(s * scale);
        sum += p;
#pragma unroll
        for (int d4 = 0; d4 < DH / 4; d4++) {
            float4 vv = Vs[j][d4];
            acc[4 * d4 + 0] += p * vv.x;
            acc[4 * d4 + 1] += p * vv.y;
            acc[4 * d4 + 2] += p * vv.z;
            acc[4 * d4 + 3] += p * vv.w;
        }
    }
    float inv = 1.f / sum;
    int tok = g_ord[b * N_TOK + c * M_CL + i];
    float* orow = o + (size_t)tok * D + hidx * DH;
#pragma unroll
    for (int d = 0; d < DH; d++) orow[d] = acc[d] * inv;
}

// ---------------- launch ----------------------------------------------------
extern "C" void kernel_launch(void* const* d_in, const int* in_sizes, int n_in,
                              void* d_out, int out_size) {
    const float* x      = (const float*)d_in[0];
    const float* pos    = (const float*)d_in[1];
    const float* ln1_g  = (const float*)d_in[2];
    const float* ln1_b  = (const float*)d_in[3];
    const float* w_qkv  = (const float*)d_in[4];
    const float* b_qkv  = (const float*)d_in[5];
    const float* w_proj = (const float*)d_in[6];
    const float* b_proj = (const float*)d_in[7];
    const float* ln2_g  = (const float*)d_in[8];
    const float* ln2_b  = (const float*)d_in[9];
    const float* w_fc1  = (const float*)d_in[10];
    const float* b_fc1  = (const float*)d_in[11];
    const float* w_fc2  = (const float*)d_in[12];
    const float* b_fc2  = (const float*)d_in[13];
    float* out = (float*)d_out;

    float *xn, *qkv, *o, *hbuf;
    int *inv;
    cudaGetSymbolAddress((void**)&xn,   g_xn);
    cudaGetSymbolAddress((void**)&qkv,  g_qkv);
    cudaGetSymbolAddress((void**)&o,    g_o);
    cudaGetSymbolAddress((void**)&hbuf, g_h);
    cudaGetSymbolAddress((void**)&inv,  g_inv);

    cudaMemcpyAsync(out, x, sizeof(float) * (size_t)BN_ROWS * D,
                    cudaMemcpyDeviceToDevice, 0);

    order_kernel<<<BN_ROWS / 256, 256>>>(pos);

    dim3 gQKV(3 * D / BN, BN_ROWS / BM);   // (9, 512)
    dim3 gPRJ(D / BN,     BN_ROWS / BM);   // (3, 512)
    dim3 gFC1(DFF / BN,   BN_ROWS / BM);   // (12, 512)
    dim3 gFC2(D / BN,     BN_ROWS / BM);   // (3, 512)
    int lnBlocks = BN_ROWS / 8;

    for (int i = 0; i < 2; i++) {
        // attention branch
        ln_kernel<<<lnBlocks, 256>>>(out, ln1_g + i * D, ln1_b + i * D, xn);
        gemm_tc<0, true, false><<<gQKV, 256>>>(
            xn, w_qkv + (size_t)i * D * 3 * D, b_qkv + i * 3 * D,
            nullptr, inv, qkv, D, 3 * D);
        attn_kernel<<<BATCH * KC * HEADS, M_CL>>>(qkv, o);
        gemm_tc<0, false, true><<<gPRJ, 256>>>(
            o, w_proj + (size_t)i * D * D, b_proj + i * D,
            out, nullptr, out, D, D);
        // MLP branch
        ln_kernel<<<lnBlocks, 256>>>(out, ln2_g + i * D, ln2_b + i * D, xn);
        gemm_tc<1, false, false><<<gFC1, 256>>>(
            xn, w_fc1 + (size_t)i * D * DFF, b_fc1 + i * DFF,
            nullptr, nullptr, hbuf, D, DFF);
        gemm_tc<0, false, true><<<gFC2, 256>>>(
            hbuf, w_fc2 + (size_t)i * DFF * D, b_fc2 + i * D,
            out, nullptr, out, DFF, D);
    }
}

// round 4
// speedup vs baseline: 2.7631x; 1.8243x over previous
#include <cuda_runtime.h>
#include <cuda_bf16.h>
#include <mma.h>
#include <math.h>

using namespace nvcuda;

#define BATCH    4
#define N_TOK    16384
#define D        192
#define DFF      768
#define HEADS    6
#define DH       32
#define M_CL     64
#define KC       (N_TOK / M_CL)
#define BN_ROWS  (BATCH * N_TOK)     // 65536
#define GRID_W   128

typedef __nv_bfloat16 bf16;

// ---------------- scratch (static device globals; no allocations) ----------
__device__ bf16  g_xn  [BN_ROWS * D];          // LN output (bf16)
__device__ bf16  g_qkv [BN_ROWS * 3 * D];      // curve-ordered qkv (bf16)
__device__ bf16  g_o   [BN_ROWS * D];          // attn out (bf16)
__device__ bf16  g_h   [BN_ROWS * DFF];        // MLP hidden (bf16)
__device__ bf16  g_wqkv[2 * D * 3 * D];
__device__ bf16  g_wprj[2 * D * D];
__device__ bf16  g_wfc1[2 * D * DFF];
__device__ bf16  g_wfc2[2 * DFF * D];
__device__ int   g_ord[BN_ROWS];               // rank  -> token row
__device__ int   g_inv[BN_ROWS];               // token -> rank row

// ---------------- fp32 -> bf16 weight conversion ----------------------------
__global__ void f2bf_kernel(const float* __restrict__ in, bf16* __restrict__ out,
                            int n) {
    int i = blockIdx.x * blockDim.x + threadIdx.x;
    if (i < n) out[i] = __float2bfloat16(in[i]);
}

// ---------------- order: keys are a permutation of 0..n-1, no sort ---------
__global__ void order_kernel(const float* __restrict__ pos) {
    int i = blockIdx.x * blockDim.x + threadIdx.x;
    if (i >= BN_ROWS) return;
    int b = i / N_TOK;
    int ix = (int)floorf(pos[(size_t)i * 2 + 0]);
    int iy = (int)floorf(pos[(size_t)i * 2 + 1]);
    int key = iy * GRID_W + ((iy & 1) ? (GRID_W - 1 - ix) : ix);
    int rank = b * N_TOK + key;
    g_inv[i]    = rank;
    g_ord[rank] = i;
}

// ---------------- layernorm: one warp per token, bf16 out ------------------
__global__ void ln_kernel(const float* __restrict__ x,
                          const float* __restrict__ gamma,
                          const float* __restrict__ beta,
                          bf16* __restrict__ out) {
    int warp = (blockIdx.x * blockDim.x + threadIdx.x) >> 5;
    int lane = threadIdx.x & 31;
    if (warp >= BN_ROWS) return;
    const float* xr = x + (size_t)warp * D;
    float v[6];
    float s = 0.f, s2 = 0.f;
#pragma unroll
    for (int j = 0; j < 6; j++) {
        v[j] = xr[lane + 32 * j];
        s += v[j];
        s2 += v[j] * v[j];
    }
#pragma unroll
    for (int o = 16; o; o >>= 1) {
        s  += __shfl_xor_sync(0xffffffffu, s,  o);
        s2 += __shfl_xor_sync(0xffffffffu, s2, o);
    }
    float mean = s * (1.f / D);
    float var  = s2 * (1.f / D) - mean * mean;
    float rstd = rsqrtf(var + 1e-5f);
    bf16* orow = out + (size_t)warp * D;
#pragma unroll
    for (int j = 0; j < 6; j++) {
        int c = lane + 32 * j;
        orow[c] = __float2bfloat16((v[j] - mean) * rstd * gamma[c] + beta[c]);
    }
}

__device__ __forceinline__ float gelu_tanh(float v) {
    float c = v + 0.044715f * v * v * v;
    return 0.5f * v * (1.f + tanhf(0.7978845608028654f * c));
}

// ---------------- bf16 tensor-core GEMM ------------------------------------
// Block tile 128x64, BK=64, 256 threads = 8 warps (4x2), warp tile 32x32,
// wmma m16n16k16 bf16, fp32 accumulate. Fused bias/act/res/scatter epilogue.
#define BM 128
#define BN 64
#define BK 64
#define LDA 72   // bf16 elements (pad 8)
#define LDB 72
#define LDC 68   // float elements (pad 4)

template <int ACT, bool SCATTER, bool RES, bool OUTBF>
__global__ __launch_bounds__(256) void gemm_bf(
        const bf16*  __restrict__ A,
        const bf16*  __restrict__ W,
        const float* __restrict__ bias,
        const float* __restrict__ res,
        const int*   __restrict__ omap,
        void* __restrict__ Cout,
        int K, int N) {
    __shared__ __align__(16) unsigned char smraw[BM * LDC * 4];  // 34816 B
    bf16*  As = (bf16*)smraw;                      // BM*LDA*2 = 18432 B
    bf16*  Bs = (bf16*)(smraw + BM * LDA * 2);     // BK*LDB*2 =  9216 B
    float* Cs = (float*)smraw;                     // epilogue stage

    int tid  = threadIdx.x;
    int warp = tid >> 5;
    int mw   = warp >> 1;
    int nw   = warp & 1;
    int mbase = blockIdx.y * BM;
    int nbase = blockIdx.x * BN;

    wmma::fragment<wmma::accumulator, 16, 16, 16, float> acc[2][2];
#pragma unroll
    for (int i = 0; i < 2; i++)
#pragma unroll
        for (int j = 0; j < 2; j++) wmma::fill_fragment(acc[i][j], 0.f);

    for (int k0 = 0; k0 < K; k0 += BK) {
        // A tile: 128x64 bf16 = 1024 uint4 loads, 4 per thread
#pragma unroll
        for (int p = 0; p < 4; p++) {
            int idx = tid + p * 256;
            int row = idx >> 3;
            int col = (idx & 7) * 8;
            *(uint4*)&As[row * LDA + col] =
                *(const uint4*)&A[(size_t)(mbase + row) * K + k0 + col];
        }
        // B tile: 64x64 bf16 = 512 uint4 loads, 2 per thread
#pragma unroll
        for (int p = 0; p < 2; p++) {
            int idx = tid + p * 256;
            int row = idx >> 3;
            int col = (idx & 7) * 8;
            *(uint4*)&Bs[row * LDB + col] =
                *(const uint4*)&W[(size_t)(k0 + row) * N + nbase + col];
        }
        __syncthreads();
#pragma unroll
        for (int kk = 0; kk < BK; kk += 16) {
            wmma::fragment<wmma::matrix_a, 16, 16, 16, bf16, wmma::row_major> af[2];
            wmma::fragment<wmma::matrix_b, 16, 16, 16, bf16, wmma::row_major> bfr[2];
#pragma unroll
            for (int i = 0; i < 2; i++)
                wmma::load_matrix_sync(af[i], &As[(mw * 32 + 16 * i) * LDA + kk], LDA);
#pragma unroll
            for (int j = 0; j < 2; j++)
                wmma::load_matrix_sync(bfr[j], &Bs[kk * LDB + nw * 32 + 16 * j], LDB);
#pragma unroll
            for (int i = 0; i < 2; i++)
#pragma unroll
                for (int j = 0; j < 2; j++)
                    wmma::mma_sync(acc[i][j], af[i], bfr[j], acc[i][j]);
        }
        __syncthreads();
    }

#pragma unroll
    for (int i = 0; i < 2; i++)
#pragma unroll
        for (int j = 0; j < 2; j++)
            wmma::store_matrix_sync(
                &Cs[(mw * 32 + 16 * i) * LDC + nw * 32 + 16 * j],
                acc[i][j], LDC, wmma::mem_row_major);
    __syncthreads();

    for (int idx = tid; idx < BM * BN; idx += 256) {
        int r  = idx >> 6;
        int cc = idx & 63;
        float v = Cs[r * LDC + cc] + bias[nbase + cc];
        if (ACT == 1) v = gelu_tanh(v);
        int orow = SCATTER ? omap[mbase + r] : (mbase + r);
        if (RES) v += res[(size_t)orow * N + nbase + cc];
        if (OUTBF)
            ((bf16*)Cout)[(size_t)orow * N + nbase + cc] = __float2bfloat16(v);
        else
            ((float*)Cout)[(size_t)orow * N + nbase + cc] = v;
    }
}

// ---------------- cluster attention: flash-style, bf16 I/O -----------------
__global__ void attn_kernel(const bf16* __restrict__ qkv,
                            bf16* __restrict__ o) {
    int hidx = blockIdx.x % HEADS;
    int rem  = blockIdx.x / HEADS;
    int c    = rem % KC;
    int b    = rem / KC;
    int i    = threadIdx.x;               // query row 0..63

    __shared__ uint4 Ks[M_CL][4];         // 64 rows x 32 bf16
    __shared__ uint4 Vs[M_CL][4];

    size_t base = (size_t)(b * N_TOK + c * M_CL) * (3 * D);
    const bf16* row = qkv + base + (size_t)i * (3 * D) + hidx * DH;

    float q[DH];
#pragma unroll
    for (int t = 0; t < 4; t++) {
        uint4 qv = ((const uint4*)row)[t];
        Ks[i][t] = ((const uint4*)(row + D))[t];
        Vs[i][t] = ((const uint4*)(row + 2 * D))[t];
        const __nv_bfloat162* h2 = (const __nv_bfloat162*)&qv;
#pragma unroll
        for (int e = 0; e < 4; e++) {
            float2 f = __bfloat1622float2(h2[e]);
            q[t * 8 + 2 * e + 0] = f.x;
            q[t * 8 + 2 * e + 1] = f.y;
        }
    }
    __syncthreads();

    const float scale = 0.17677669529663687f;   // 1/sqrt(32)
    float acc[DH];
#pragma unroll
    for (int d = 0; d < DH; d++) acc[d] = 0.f;
    float sum = 0.f;

#pragma unroll 2
    for (int j = 0; j < M_CL; j++) {
        float s = 0.f;
#pragma unroll
        for (int t = 0; t < 4; t++) {
            uint4 kv = Ks[j][t];
            const __nv_bfloat162* h2 = (const __nv_bfloat162*)&kv;
#pragma unroll
            for (int e = 0; e < 4; e++) {
                float2 f = __bfloat1622float2(h2[e]);
                s += q[t * 8 + 2 * e] * f.x + q[t * 8 + 2 * e + 1] * f.y;
            }
        }
        float p = __expf(s * scale);
        sum += p;
#pragma unroll
        for (int t = 0; t < 4; t++) {
            uint4 vv = Vs[j][t];
            const __nv_bfloat162* h2 = (const __nv_bfloat162*)&vv;
#pragma unroll
            for (int e = 0; e < 4; e++) {
                float2 f = __bfloat1622float2(h2[e]);
                acc[t * 8 + 2 * e + 0] += p * f.x;
                acc[t * 8 + 2 * e + 1] += p * f.y;
            }
        }
    }
    float inv = 1.f / sum;
    int tok = g_ord[b * N_TOK + c * M_CL + i];
    bf16* orow = o + (size_t)tok * D + hidx * DH;
#pragma unroll
    for (int d = 0; d < DH; d++) orow[d] = __float2bfloat16(acc[d] * inv);
}

// ---------------- launch ----------------------------------------------------
extern "C" void kernel_launch(void* const* d_in, const int* in_sizes, int n_in,
                              void* d_out, int out_size) {
    const float* x      = (const float*)d_in[0];
    const float* pos    = (const float*)d_in[1];
    const float* ln1_g  = (const float*)d_in[2];
    const float* ln1_b  = (const float*)d_in[3];
    const float* w_qkv  = (const float*)d_in[4];
    const float* b_qkv  = (const float*)d_in[5];
    const float* w_proj = (const float*)d_in[6];
    const float* b_proj = (const float*)d_in[7];
    const float* ln2_g  = (const float*)d_in[8];
    const float* ln2_b  = (const float*)d_in[9];
    const float* w_fc1  = (const float*)d_in[10];
    const float* b_fc1  = (const float*)d_in[11];
    const float* w_fc2  = (const float*)d_in[12];
    const float* b_fc2  = (const float*)d_in[13];
    float* out = (float*)d_out;

    bf16 *xn, *qkv, *o, *hbuf, *wqkv, *wprj, *wfc1, *wfc2;
    int *inv;
    cudaGetSymbolAddress((void**)&xn,   g_xn);
    cudaGetSymbolAddress((void**)&qkv,  g_qkv);
    cudaGetSymbolAddress((void**)&o,    g_o);
    cudaGetSymbolAddress((void**)&hbuf, g_h);
    cudaGetSymbolAddress((void**)&wqkv, g_wqkv);
    cudaGetSymbolAddress((void**)&wprj, g_wprj);
    cudaGetSymbolAddress((void**)&wfc1, g_wfc1);
    cudaGetSymbolAddress((void**)&wfc2, g_wfc2);
    cudaGetSymbolAddress((void**)&inv,  g_inv);

    cudaMemcpyAsync(out, x, sizeof(float) * (size_t)BN_ROWS * D,
                    cudaMemcpyDeviceToDevice, 0);

    // weight conversion (runs every launch; deterministic, tiny)
    f2bf_kernel<<<(2 * D * 3 * D + 255) / 256, 256>>>(w_qkv,  wqkv, 2 * D * 3 * D);
    f2bf_kernel<<<(2 * D * D     + 255) / 256, 256>>>(w_proj, wprj, 2 * D * D);
    f2bf_kernel<<<(2 * D * DFF   + 255) / 256, 256>>>(w_fc1,  wfc1, 2 * D * DFF);
    f2bf_kernel<<<(2 * DFF * D   + 255) / 256, 256>>>(w_fc2,  wfc2, 2 * DFF * D);

    order_kernel<<<BN_ROWS / 256, 256>>>(pos);

    dim3 gQKV(3 * D / BN, BN_ROWS / BM);   // (9, 512)
    dim3 gPRJ(D / BN,     BN_ROWS / BM);   // (3, 512)
    dim3 gFC1(DFF / BN,   BN_ROWS / BM);   // (12, 512)
    dim3 gFC2(D / BN,     BN_ROWS / BM);   // (3, 512)
    int lnBlocks = BN_ROWS / 8;

    for (int i = 0; i < 2; i++) {
        // attention branch
        ln_kernel<<<lnBlocks, 256>>>(out, ln1_g + i * D, ln1_b + i * D, xn);
        gemm_bf<0, true, false, true><<<gQKV, 256>>>(
            xn, wqkv + (size_t)i * D * 3 * D, b_qkv + i * 3 * D,
            nullptr, inv, qkv, D, 3 * D);
        attn_kernel<<<BATCH * KC * HEADS, M_CL>>>(qkv, o);
        gemm_bf<0, false, true, false><<<gPRJ, 256>>>(
            o, wprj + (size_t)i * D * D, b_proj + i * D,
            out, nullptr, out, D, D);
        // MLP branch
        ln_kernel<<<lnBlocks, 256>>>(out, ln2_g + i * D, ln2_b + i * D, xn);
        gemm_bf<1, false, false, true><<<gFC1, 256>>>(
            xn, wfc1 + (size_t)i * D * DFF, b_fc1 + i * DFF,
            nullptr, nullptr, hbuf, D, DFF);
        gemm_bf<0, false, true, false><<<gFC2, 256>>>(
            hbuf, wfc2 + (size_t)i * DFF * D, b_fc2 + i * D,
            out, nullptr, out, DFF, D);
    }
}